// round 5
// baseline (speedup 1.0000x reference)
#include <cuda_runtime.h>
#include <math.h>
#include <stdint.h>

// ---------------- constants ----------------
#define K2        72.13475204444817f     // (1/EPS)*log2(e)
#define TWOK2     144.26950408889634f    // 2*K2
#define EPS_LN2   0.013862943611198906f  // EPS*ln(2) == 1/K2
#define EPSLOG1024 0.13862943611198905f
#define EPSLOG4096 0.16635532333438687f
#define ROWSB     56
#define IDENT_MASK 0x7FFFFFFF
typedef unsigned long long ull;

// ---------------- scratch ----------------
__device__ float g_gtfps[2 * 1024 * 3];
__device__ float g_f1[2 * 1024];
__device__ float g_g1[2 * 1024];
__device__ float g_f2[2 * 4096];
__device__ float g_g2[2 * 4096];
__device__ float g_emd1r[2 * 1024];
__device__ float g_emd2r[2 * 4096];
__device__ float g_d1c[2 * 4096];
__device__ float g_d2c[2 * 512];
__device__ float g_d1f[2 * 4096];
__device__ float g_d2f[2 * 4096];

// ---------------- fast math helpers ----------------
__device__ __forceinline__ float ex2(float x) {
    float y; asm("ex2.approx.ftz.f32 %0, %1;" : "=f"(y) : "f"(x)); return y;
}
__device__ __forceinline__ float lg2(float x) {
    float y; asm("lg2.approx.f32 %0, %1;" : "=f"(y) : "f"(x)); return y;
}
__device__ __forceinline__ ull pack2(float a, float b) {
    ull r; asm("mov.b64 %0, {%1, %2};" : "=l"(r) : "f"(a), "f"(b)); return r;
}
__device__ __forceinline__ void unpack2(ull v, float& a, float& b) {
    asm("mov.b64 {%0, %1}, %2;" : "=f"(a), "=f"(b) : "l"(v));
}
__device__ __forceinline__ ull fma2(ull a, ull b, ull c) {
    ull d; asm("fma.rn.f32x2 %0, %1, %2, %3;" : "=l"(d) : "l"(a), "l"(b), "l"(c)); return d;
}
__device__ __forceinline__ ull add2(ull a, ull b) {
    ull d; asm("add.rn.f32x2 %0, %1, %2;" : "=l"(d) : "l"(a), "l"(b)); return d;
}
__device__ __forceinline__ void lds2u64(unsigned addr, ull& a, ull& b) {
    asm volatile("ld.shared.v2.u64 {%0, %1}, [%2];" : "=l"(a), "=l"(b) : "r"(addr));
}

// ---------------- FPS: 1024 threads, 4 pts/thread, 1 barrier/step ----------------
__global__ __launch_bounds__(1024) void fps_kernel(const float* __restrict__ gt) {
    extern __shared__ float sh[];
    float* SX = sh;
    float* SY = sh + 4096;
    float* SZ = sh + 8192;
    int* swv = (int*)(sh + 12288);
    int* swi = (int*)(sh + 12288) + 64;

    int b = blockIdx.x;
    const float* P = gt + b * 4096 * 3;
    float* outp = g_gtfps + b * 1024 * 3;
    int t = threadIdx.x, lane = t & 31, wid = t >> 5;

    const float4* P4 = (const float4*)P;
    for (int k = t; k < 3072; k += 1024) {
        float4 v = P4[k];
        int e = 4 * k;
        float c[4] = {v.x, v.y, v.z, v.w};
#pragma unroll
        for (int q = 0; q < 4; q++) {
            int ei = e + q;
            sh[(ei % 3) * 4096 + (ei / 3)] = c[q];
        }
    }
    __syncthreads();

    int base = t * 4;
    ull pX[2], pY[2], pZ[2], pP[2];
    float dm[4];
#pragma unroll
    for (int j = 0; j < 2; j++) {
        float x0 = SX[base + 2 * j], x1 = SX[base + 2 * j + 1];
        float y0 = SY[base + 2 * j], y1 = SY[base + 2 * j + 1];
        float z0 = SZ[base + 2 * j], z1 = SZ[base + 2 * j + 1];
        pX[j] = pack2(x0, x1); pY[j] = pack2(y0, y1); pZ[j] = pack2(z0, z1);
        pP[j] = pack2(fmaf(z0, z0, fmaf(y0, y0, x0 * x0)),
                      fmaf(z1, z1, fmaf(y1, y1, x1 * x1)));
        dm[2 * j] = 1e10f; dm[2 * j + 1] = 1e10f;
    }

    float lx = SX[0], ly = SY[0], lz = SZ[0];
    if (t == 0) { outp[0] = lx; outp[1] = ly; outp[2] = lz; }

    for (int step = 1; step < 1024; step++) {
        int par = step & 1;
        float ll = fmaf(lz, lz, fmaf(ly, ly, lx * lx));
        ull n2x = pack2(-2.0f * lx, -2.0f * lx);
        ull n2y = pack2(-2.0f * ly, -2.0f * ly);
        ull n2z = pack2(-2.0f * lz, -2.0f * lz);
        ull ll2 = pack2(ll, ll);
#pragma unroll
        for (int j = 0; j < 2; j++) {
            ull acc = fma2(pX[j], n2x, pP[j]);
            acc = fma2(pY[j], n2y, acc);
            acc = fma2(pZ[j], n2z, acc);
            acc = add2(acc, ll2);
            float d0, d1; unpack2(acc, d0, d1);
            dm[2 * j]     = fminf(dm[2 * j], d0);
            dm[2 * j + 1] = fminf(dm[2 * j + 1], d1);
        }
        float bv = dm[0]; int bs = 0;
#pragma unroll
        for (int m = 1; m < 4; m++)
            if (dm[m] > bv) { bv = dm[m]; bs = m; }
        int mb = __float_as_int(bv);
        int M = __reduce_max_sync(0xffffffffu, mb);
        unsigned mk = __ballot_sync(0xffffffffu, mb == M);
        int src = __ffs(mk) - 1;
        int widx = __shfl_sync(0xffffffffu, base + bs, src);
        if (lane == 0) { swv[par * 32 + wid] = M; swi[par * 32 + wid] = widx; }
        __syncthreads();
        int v  = swv[par * 32 + lane];
        int id = swi[par * 32 + lane];
        int M2 = __reduce_max_sync(0xffffffffu, v);
        unsigned mk2 = __ballot_sync(0xffffffffu, v == M2);
        int s2 = __ffs(mk2) - 1;
        int bi = __shfl_sync(0xffffffffu, id, s2);
        lx = SX[bi]; ly = SY[bi]; lz = SZ[bi];
        if (t == 0) {
            outp[step * 3 + 0] = lx; outp[step * 3 + 1] = ly; outp[step * 3 + 2] = lz;
        }
    }
}

// ---------------- pairwise kernel: pair-packed f32x2, two-pass LSE ----------------
// Layout: shA[p] = {x0,x1,y0,y1}, shB[p] = {z0,z1,w0,w1} (pair p = points 2p,2p+1)
// MODE 0: Sinkhorn half-pass; MODE 1: final EMD row; MODE 2: chamfer min
template <int MODE>
__global__ __launch_bounds__(1024) void pair_kernel(
    const float* __restrict__ Pbase, int Np, int maskP, int strideP,
    const float* __restrict__ Qbase, int Nq, int maskQ, int strideQ,
    const float* __restrict__ vinBase, float* __restrict__ voutBase,
    float epsLogN, const int* __restrict__ itersPtr, int myIter)
{
    if (itersPtr && myIter >= *itersPtr) return;
    int b = blockIdx.y;
    const float* P = Pbase + b * strideP;
    const float* Q = Qbase + b * strideQ;
    const float* vin = vinBase ? (vinBase + b * Nq) : nullptr;

    extern __shared__ float sh[];
    float* shA = sh;
    float* shB = sh + 2 * Nq;
    float* shG = sh + 4 * Nq;   // MODE 1 only

    for (int j = threadIdx.x; j < Nq; j += blockDim.x) {
        int qj = j & maskQ;
        float qx = Q[qj * 3], qy = Q[qj * 3 + 1], qz = Q[qj * 3 + 2];
        float qw = fmaf(qz, qz, fmaf(qy, qy, qx * qx));
        int p = j >> 1, h = j & 1;
        if (MODE == 2) {
            shA[4 * p + h]     = qx;
            shA[4 * p + 2 + h] = qy;
            shB[4 * p + h]     = qz;
            shB[4 * p + 2 + h] = qw;
        } else {
            float gq = vin ? fmaf(-K2, qw, vin[j] * K2) : (-K2 * qw);
            shA[4 * p + h]     = qx * TWOK2;
            shA[4 * p + 2 + h] = qy * TWOK2;
            shB[4 * p + h]     = qz * TWOK2;
            shB[4 * p + 2 + h] = gq;
            if (MODE == 1) shG[2 * p + h] = vin[j] * K2;
        }
    }
    __syncthreads();

    int warp = threadIdx.x >> 5, lane = threadIdx.x & 31;
    int rsub = lane >> 4, jsub = lane & 15;
    int rowInBlk = warp * 2 + rsub;
    int i = blockIdx.x * ROWSB + rowInBlk;
    if (rowInBlk >= ROWSB || i >= Np) return;
    int pi = i & maskP;
    float px = P[pi * 3], py = P[pi * 3 + 1], pz = P[pi * 3 + 2];
    float x2 = fmaf(pz, pz, fmaf(py, py, px * px));

    unsigned sbase = (unsigned)__cvta_generic_to_shared(sh);
    unsigned sA0 = sbase + (jsub << 4);
    unsigned sB0 = sbase + 8 * (unsigned)Nq + (jsub << 4);
    int P2 = Nq >> 1;

    if (MODE == 2) {
        ull nx = pack2(-2.0f * px, -2.0f * px);
        ull ny = pack2(-2.0f * py, -2.0f * py);
        ull nz = pack2(-2.0f * pz, -2.0f * pz);
        float mn = 3.4e38f;
        unsigned aA = sA0, aB = sB0;
#pragma unroll 4
        for (int p = jsub; p < P2; p += 16, aA += 256, aB += 256) {
            ull ax, ay, az, bw;
            lds2u64(aA, ax, ay);
            lds2u64(aB, az, bw);
            ull acc = fma2(ax, nx, bw);
            acc = fma2(ay, ny, acc);
            acc = fma2(az, nz, acc);
            float t0, t1; unpack2(acc, t0, t1);
            mn = fminf(mn, fminf(t0, t1));
        }
#pragma unroll
        for (int off = 8; off; off >>= 1)
            mn = fminf(mn, __shfl_xor_sync(0xffffffffu, mn, off));
        if (jsub == 0) voutBase[b * Np + i] = fmaxf(mn + x2, 0.0f);
        return;
    }

    // MODE 0 / 1: r = w + (2k q)·p ; t2 = r + a0 ; a0 = -k|p|^2
    ull px2 = pack2(px, px), py2 = pack2(py, py), pz2 = pack2(pz, pz);
    float a0 = -K2 * x2;

    // pass 1: exact row max of r (branchless)
    float m = -1e30f;
    {
        unsigned aA = sA0, aB = sB0;
#pragma unroll 4
        for (int p = jsub; p < P2; p += 16, aA += 256, aB += 256) {
            ull ax, ay, az, bw;
            lds2u64(aA, ax, ay);
            lds2u64(aB, az, bw);
            ull acc = fma2(ax, px2, bw);
            acc = fma2(ay, py2, acc);
            acc = fma2(az, pz2, acc);
            float t0, t1; unpack2(acc, t0, t1);
            m = fmaxf(m, fmaxf(t0, t1));
        }
#pragma unroll
        for (int off = 8; off; off >>= 1)
            m = fmaxf(m, __shfl_xor_sync(0xffffffffu, m, off));
    }

    if (MODE == 0) {
        // pass 2: unconditional exp-sum
        ull nm2 = pack2(-m, -m);
        float s0 = 0.0f, s1 = 0.0f;
        unsigned aA = sA0, aB = sB0;
#pragma unroll 4
        for (int p = jsub; p < P2; p += 16, aA += 256, aB += 256) {
            ull ax, ay, az, bw;
            lds2u64(aA, ax, ay);
            lds2u64(aB, az, bw);
            ull acc = fma2(ax, px2, bw);
            acc = fma2(ay, py2, acc);
            acc = fma2(az, pz2, acc);
            acc = add2(acc, nm2);
            float t0, t1; unpack2(acc, t0, t1);
            s0 += ex2(t0);
            s1 += ex2(t1);
        }
        float s = s0 + s1;
#pragma unroll
        for (int off = 8; off; off >>= 1)
            s += __shfl_xor_sync(0xffffffffu, s, off);
        if (jsub == 0)
            voutBase[b * Np + i] = fmaf(-EPS_LN2, (m + a0) + lg2(s), -epsLogN);
        return;
    }

    if (MODE == 1) {
        ull nm2 = pack2(-m, -m);
        float cbase = -(m + a0) * EPS_LN2;     // C = (gk - u)*EPS_LN2 + cbase - gk term below
        float s = 0.0f, sc = 0.0f;
        unsigned aA = sA0, aB = sB0;
        unsigned aG = sbase + 16 * (unsigned)Nq + (jsub << 3);
#pragma unroll 2
        for (int p = jsub; p < P2; p += 16, aA += 256, aB += 256, aG += 128) {
            ull ax, ay, az, bw;
            lds2u64(aA, ax, ay);
            lds2u64(aB, az, bw);
            ull acc = fma2(ax, px2, bw);
            acc = fma2(ay, py2, acc);
            acc = fma2(az, pz2, acc);
            acc = add2(acc, nm2);
            float u0, u1; unpack2(acc, u0, u1);
            float2 gv = *(float2*)((char*)sh + ((16u * (unsigned)Nq + ((unsigned)p << 3)) ));
            float e0 = ex2(u0), e1 = ex2(u1);
            float C0 = fmaf(gv.x - u0, EPS_LN2, cbase);
            float C1 = fmaf(gv.y - u1, EPS_LN2, cbase);
            s += e0; s += e1;
            sc = fmaf(e0, C0, sc);
            sc = fmaf(e1, C1, sc);
        }
#pragma unroll
        for (int off = 8; off; off >>= 1) {
            s  += __shfl_xor_sync(0xffffffffu, s, off);
            sc += __shfl_xor_sync(0xffffffffu, sc, off);
        }
        if (jsub == 0) voutBase[b * Np + i] = sqrtf(sc / s);
    }
}

// ---------------- reductions / final scalar outputs ----------------
__device__ __forceinline__ float blk_sum(float v, float* shp) {
    int lane = threadIdx.x & 31, wid = threadIdx.x >> 5;
#pragma unroll
    for (int off = 16; off; off >>= 1) v += __shfl_xor_sync(0xffffffffu, v, off);
    if (lane == 0) shp[wid] = v;
    __syncthreads();
    float r = 0.0f;
    if (wid == 0) {
        r = shp[lane];
#pragma unroll
        for (int off = 16; off; off >>= 1) r += __shfl_xor_sync(0xffffffffu, r, off);
    }
    __syncthreads();
    return r;
}

__global__ __launch_bounds__(1024) void finalize_kernel(float* __restrict__ out) {
    __shared__ float shp[32];
    int b = blockIdx.x;
    int t = threadIdx.x;
    const int BASE = 27648;

    float v = g_emd1r[b * 1024 + t];
    v = blk_sum(v, shp);
    if (t == 0) out[BASE + 0 + b] = v * (1.0f / 1024.0f);

    v = 0.0f;
    for (int i = t; i < 4096; i += 1024) v += g_emd2r[b * 4096 + i];
    v = blk_sum(v, shp);
    if (t == 0) out[BASE + 2 + b] = v * (1.0f / 4096.0f);

    float vs = 0.0f, vt = 0.0f;
    for (int i = t; i < 4096; i += 1024) { float d = g_d1c[b * 4096 + i]; vs += sqrtf(d); vt += d; }
    vs = blk_sum(vs, shp); vt = blk_sum(vt, shp);
    float vs2 = 0.0f, vt2 = 0.0f;
    if (t < 512) { float d = g_d2c[b * 512 + t]; vs2 = sqrtf(d); vt2 = d; }
    vs2 = blk_sum(vs2, shp); vt2 = blk_sum(vt2, shp);
    if (t == 0) {
        out[BASE + 4 + b] = (vs * (1.0f / 4096.0f) + vs2 * (1.0f / 512.0f)) * 0.5f;
        out[BASE + 8 + b] = vt * (1.0f / 4096.0f) + vt2 * (1.0f / 512.0f);
    }

    vs = 0.0f; vt = 0.0f;
    for (int i = t; i < 4096; i += 1024) { float d = g_d1f[b * 4096 + i]; vs += sqrtf(d); vt += d; }
    vs = blk_sum(vs, shp); vt = blk_sum(vt, shp);
    vs2 = 0.0f; vt2 = 0.0f;
    for (int i = t; i < 4096; i += 1024) { float d = g_d2f[b * 4096 + i]; vs2 += sqrtf(d); vt2 += d; }
    vs2 = blk_sum(vs2, shp); vt2 = blk_sum(vt2, shp);
    if (t == 0) {
        out[BASE + 6 + b]  = (vs + vs2) * (1.0f / 4096.0f) * 0.5f;
        out[BASE + 10 + b] = (vt + vt2) * (1.0f / 4096.0f);
    }
}

// ---------------- launch ----------------
extern "C" void kernel_launch(void* const* d_in, const int* in_sizes, int n_in,
                              void* d_out, int out_size) {
    const float* coarse = (const float*)d_in[0];
    const float* fine   = (const float*)d_in[1];
    const float* gt     = (const float*)d_in[2];
    const int*   iters  = (const int*)d_in[3];
    float* out = (float*)d_out;

    static cudaStream_t s1 = nullptr;
    static cudaEvent_t evFork = nullptr, evJoin = nullptr;
    if (!s1) {
        cudaStreamCreateWithFlags(&s1, cudaStreamNonBlocking);
        cudaEventCreateWithFlags(&evFork, cudaEventDisableTiming);
        cudaEventCreateWithFlags(&evJoin, cudaEventDisableTiming);
        cudaFuncSetAttribute(pair_kernel<0>, cudaFuncAttributeMaxDynamicSharedMemorySize, 84000);
        cudaFuncSetAttribute(pair_kernel<1>, cudaFuncAttributeMaxDynamicSharedMemorySize, 84000);
        cudaFuncSetAttribute(pair_kernel<2>, cudaFuncAttributeMaxDynamicSharedMemorySize, 84000);
        cudaFuncSetAttribute(fps_kernel,     cudaFuncAttributeMaxDynamicSharedMemorySize, 50000);
    }

    float *gtfps, *f1, *g1, *f2, *g2, *e1r, *e2r, *d1c, *d2c, *d1f, *d2f;
    cudaGetSymbolAddress((void**)&gtfps, g_gtfps);
    cudaGetSymbolAddress((void**)&f1, g_f1);
    cudaGetSymbolAddress((void**)&g1, g_g1);
    cudaGetSymbolAddress((void**)&f2, g_f2);
    cudaGetSymbolAddress((void**)&g2, g_g2);
    cudaGetSymbolAddress((void**)&e1r, g_emd1r);
    cudaGetSymbolAddress((void**)&e2r, g_emd2r);
    cudaGetSymbolAddress((void**)&d1c, g_d1c);
    cudaGetSymbolAddress((void**)&d2c, g_d2c);
    cudaGetSymbolAddress((void**)&d1f, g_d1f);
    cudaGetSymbolAddress((void**)&d2f, g_d2f);

    // ---- fork first: FPS + EMD1 on s1 (no init dependency; first pass vin=NULL) ----
    cudaEventRecord(evFork, 0);
    cudaStreamWaitEvent(s1, evFork, 0);
    fps_kernel<<<2, 1024, 50000, s1>>>(gt);

    cudaMemcpyAsync(out,        coarse, 2 * 512 * 3 * sizeof(float),  cudaMemcpyDeviceToDevice);
    cudaMemcpyAsync(out + 3072, fine,   2 * 4096 * 3 * sizeof(float), cudaMemcpyDeviceToDevice);

    // ---- stream 0: EMD2 chain (grid 74 x 2 = one block per SM) ----
    const int GX4 = (4096 + ROWSB - 1) / ROWSB;   // 74
    const int GX1 = (1024 + ROWSB - 1) / ROWSB;   // 19
    const int GXC = (512 + ROWSB - 1) / ROWSB;    // 10
    for (int it = 0; it < 4; it++) {
        pair_kernel<0><<<dim3(GX4, 2), 1024, 4096 * 16>>>(
            fine, 4096, IDENT_MASK, 4096 * 3, gt, 4096, IDENT_MASK, 4096 * 3,
            it == 0 ? nullptr : g2, f2, EPSLOG4096, iters, it);
        pair_kernel<0><<<dim3(GX4, 2), 1024, 4096 * 16>>>(
            gt, 4096, IDENT_MASK, 4096 * 3, fine, 4096, IDENT_MASK, 4096 * 3,
            f2, g2, EPSLOG4096, iters, it);
    }
    pair_kernel<1><<<dim3(GX4, 2), 1024, 4096 * 20>>>(
        fine, 4096, IDENT_MASK, 4096 * 3, gt, 4096, IDENT_MASK, 4096 * 3,
        g2, e2r, 0.0f, nullptr, 0);

    // ---- stream 0: chamfers ----
    pair_kernel<2><<<dim3(GX4, 2), 1024, 512 * 16>>>(
        gt, 4096, IDENT_MASK, 4096 * 3, coarse, 512, IDENT_MASK, 512 * 3,
        nullptr, d1c, 0.0f, nullptr, 0);
    pair_kernel<2><<<dim3(GXC, 2), 1024, 4096 * 16>>>(
        coarse, 512, IDENT_MASK, 512 * 3, gt, 4096, IDENT_MASK, 4096 * 3,
        nullptr, d2c, 0.0f, nullptr, 0);
    pair_kernel<2><<<dim3(GX4, 2), 1024, 4096 * 16>>>(
        gt, 4096, IDENT_MASK, 4096 * 3, fine, 4096, IDENT_MASK, 4096 * 3,
        nullptr, d1f, 0.0f, nullptr, 0);
    pair_kernel<2><<<dim3(GX4, 2), 1024, 4096 * 16>>>(
        fine, 4096, IDENT_MASK, 4096 * 3, gt, 4096, IDENT_MASK, 4096 * 3,
        nullptr, d2f, 0.0f, nullptr, 0);

    // ---- s1: EMD1 chain (after FPS) ----
    for (int it = 0; it < 4; it++) {
        pair_kernel<0><<<dim3(GX1, 2), 1024, 1024 * 16, s1>>>(
            coarse, 1024, 511, 512 * 3, gtfps, 1024, IDENT_MASK, 1024 * 3,
            it == 0 ? nullptr : g1, f1, EPSLOG1024, iters, it);
        pair_kernel<0><<<dim3(GX1, 2), 1024, 1024 * 16, s1>>>(
            gtfps, 1024, IDENT_MASK, 1024 * 3, coarse, 1024, 511, 512 * 3,
            f1, g1, EPSLOG1024, iters, it);
    }
    pair_kernel<1><<<dim3(GX1, 2), 1024, 1024 * 20, s1>>>(
        coarse, 1024, 511, 512 * 3, gtfps, 1024, IDENT_MASK, 1024 * 3,
        g1, e1r, 0.0f, nullptr, 0);

    // ---- join, finalize ----
    cudaEventRecord(evJoin, s1);
    cudaStreamWaitEvent(0, evJoin, 0);
    finalize_kernel<<<2, 1024>>>(out);
}

// round 7
// speedup vs baseline: 1.4956x; 1.4956x over previous
#include <cuda_runtime.h>
#include <math.h>
#include <stdint.h>

// ---------------- constants ----------------
#define K2        72.13475204444817f     // (1/EPS)*log2(e)
#define TWOK2     144.26950408889634f    // 2*K2
#define EPS_LN2   0.013862943611198906f  // EPS*ln(2) == 1/K2
#define EPSLOG1024 0.13862943611198905f
#define EPSLOG4096 0.16635532333438687f
#define ROWSB     64
#define IDENT_MASK 0x7FFFFFFF
typedef unsigned long long ull;

// ---------------- scratch ----------------
__device__ float g_gtfps[2 * 1024 * 3];
__device__ float g_f1[2 * 1024];
__device__ float g_g1[2 * 1024];
__device__ float g_f2[2 * 4096];
__device__ float g_g2[2 * 4096];
__device__ float g_emd1r[2 * 1024];
__device__ float g_emd2r[2 * 4096];
__device__ float g_d1c[2 * 4096];
__device__ float g_d2c[2 * 512];
__device__ float g_d1f[2 * 4096];
__device__ float g_d2f[2 * 4096];

// ---------------- fast math helpers ----------------
__device__ __forceinline__ float ex2(float x) {
    float y; asm("ex2.approx.ftz.f32 %0, %1;" : "=f"(y) : "f"(x)); return y;
}
__device__ __forceinline__ float lg2(float x) {
    float y; asm("lg2.approx.f32 %0, %1;" : "=f"(y) : "f"(x)); return y;
}
__device__ __forceinline__ ull pack2(float a, float b) {
    ull r; asm("mov.b64 %0, {%1, %2};" : "=l"(r) : "f"(a), "f"(b)); return r;
}
__device__ __forceinline__ void unpack2(ull v, float& a, float& b) {
    asm("mov.b64 {%0, %1}, %2;" : "=f"(a), "=f"(b) : "l"(v));
}
__device__ __forceinline__ ull fma2(ull a, ull b, ull c) {
    ull d; asm("fma.rn.f32x2 %0, %1, %2, %3;" : "=l"(d) : "l"(a), "l"(b), "l"(c)); return d;
}
__device__ __forceinline__ ull add2(ull a, ull b) {
    ull d; asm("add.rn.f32x2 %0, %1, %2;" : "=l"(d) : "l"(a), "l"(b)); return d;
}
__device__ __forceinline__ void lds2u64(unsigned addr, ull& a, ull& b) {
    asm volatile("ld.shared.v2.u64 {%0, %1}, [%2];" : "=l"(a), "=l"(b) : "r"(addr));
}

// ---------------- FPS: 128 threads, 32 pts/thread in registers ----------------
// Value-only reductions; winner index via rare scan + atomicMin (lowest index
// tie-break = jnp.argmax semantics, ownership is contiguous).
#define FPS_T 128
__global__ __launch_bounds__(FPS_T) void fps_kernel(const float* __restrict__ gt) {
    extern __shared__ float sh[];
    float* SX = sh;
    float* SY = sh + 4096;
    float* SZ = sh + 8192;
    int* swm  = (int*)(sh + 12288);   // [4] per-warp max bits
    int* sIdx = (int*)(sh + 12292);   // [2] winner idx, parity dbl-buffered

    int b = blockIdx.x;
    const float* P = gt + b * 4096 * 3;
    float* outp = g_gtfps + b * 1024 * 3;
    int t = threadIdx.x, lane = t & 31, wid = t >> 5;

    const float4* P4 = (const float4*)P;
    for (int k = t; k < 3072; k += FPS_T) {
        float4 v = P4[k];
        int e = 4 * k;
        float c[4] = {v.x, v.y, v.z, v.w};
#pragma unroll
        for (int q = 0; q < 4; q++) {
            int ei = e + q;
            sh[(ei % 3) * 4096 + (ei / 3)] = c[q];
        }
    }
    if (t == 0) { sIdx[0] = 0x7FFFFFFF; sIdx[1] = 0x7FFFFFFF; }
    __syncthreads();

    int base = t * 32;                      // contiguous ownership
    ull qx[16], qy[16], qz[16], qw[16];
    float dm[32];
#pragma unroll
    for (int j = 0; j < 16; j++) {
        float x0 = SX[base + 2 * j], x1 = SX[base + 2 * j + 1];
        float y0 = SY[base + 2 * j], y1 = SY[base + 2 * j + 1];
        float z0 = SZ[base + 2 * j], z1 = SZ[base + 2 * j + 1];
        qx[j] = pack2(x0, x1); qy[j] = pack2(y0, y1); qz[j] = pack2(z0, z1);
        qw[j] = pack2(fmaf(z0, z0, fmaf(y0, y0, x0 * x0)),
                      fmaf(z1, z1, fmaf(y1, y1, x1 * x1)));
        dm[2 * j] = 1e10f; dm[2 * j + 1] = 1e10f;
    }

    float lx = SX[0], ly = SY[0], lz = SZ[0];
    if (t == 0) { outp[0] = lx; outp[1] = ly; outp[2] = lz; }

    for (int step = 1; step < 1024; step++) {
        float ll = fmaf(lz, lz, fmaf(ly, ly, lx * lx));
        ull nx = pack2(-2.0f * lx, -2.0f * lx);
        ull ny = pack2(-2.0f * ly, -2.0f * ly);
        ull nz = pack2(-2.0f * lz, -2.0f * lz);
        ull l2 = pack2(ll, ll);
        float mv = -1.0f;
#pragma unroll
        for (int j = 0; j < 16; j++) {
            ull d = fma2(qx[j], nx, qw[j]);
            d = fma2(qy[j], ny, d);
            d = fma2(qz[j], nz, d);
            d = add2(d, l2);
            float d0, d1; unpack2(d, d0, d1);
            dm[2 * j]     = fminf(dm[2 * j], d0);
            dm[2 * j + 1] = fminf(dm[2 * j + 1], d1);
            mv = fmaxf(mv, fmaxf(dm[2 * j], dm[2 * j + 1]));
        }
        int mb = __float_as_int(mv);               // d>=0 -> bits monotone
        int M = __reduce_max_sync(0xffffffffu, mb);
        if (lane == 0) swm[wid] = M;
        __syncthreads();
        int MM = max(max(swm[0], swm[1]), max(swm[2], swm[3]));
        if (mb == MM) {                            // winning thread(s) only
            float Mf = __int_as_float(MM);
            int idx = 0x7FFFFFFF;
#pragma unroll
            for (int j = 31; j >= 0; j--)
                if (dm[j] == Mf) idx = base + j;   // downward scan -> lowest idx
            atomicMin(&sIdx[step & 1], idx);
        }
        __syncthreads();
        int wi = sIdx[step & 1];
        lx = SX[wi]; ly = SY[wi]; lz = SZ[wi];
        if (t == 0) {
            outp[step * 3 + 0] = lx; outp[step * 3 + 1] = ly; outp[step * 3 + 2] = lz;
            sIdx[(step + 1) & 1] = 0x7FFFFFFF;     // reset other slot (2 bars before reuse)
        }
    }
}

// ---------------- pairwise kernel: 4 rows/warp, pair-packed f32x2 ----------------
// smem: shA[p]={x0,x1,y0,y1}*TWOK2, shB[p]={z0,z1,(w0,w1)} w = K2*g - K2*|q|^2
// MODE 0: Sinkhorn half-pass (online-flat LSE + warp-vote skip)
// MODE 1: final EMD row; MODE 2: chamfer min
template <int MODE>
__global__ __launch_bounds__(512) void pair_kernel(
    const float* __restrict__ Pbase, int Np, int maskP, int strideP,
    const float* __restrict__ Qbase, int Nq, int maskQ, int strideQ,
    const float* __restrict__ vinBase, float* __restrict__ voutBase,
    float epsLogN, const int* __restrict__ itersPtr, int myIter)
{
    if (itersPtr && myIter >= *itersPtr) return;
    int b = blockIdx.y;
    const float* P = Pbase + b * strideP;
    const float* Q = Qbase + b * strideQ;
    const float* vin = vinBase ? (vinBase + b * Nq) : nullptr;

    extern __shared__ float sh[];
    float* shA = sh;
    float* shB = sh + 2 * Nq;
    float* shG = sh + 4 * Nq;   // MODE 1 only

    for (int j = threadIdx.x; j < Nq; j += blockDim.x) {
        int qj = j & maskQ;
        float qx = Q[qj * 3], qy = Q[qj * 3 + 1], qz = Q[qj * 3 + 2];
        float qw = fmaf(qz, qz, fmaf(qy, qy, qx * qx));
        int p = j >> 1, h = j & 1;
        if (MODE == 2) {
            shA[4 * p + h]     = qx;
            shA[4 * p + 2 + h] = qy;
            shB[4 * p + h]     = qz;
            shB[4 * p + 2 + h] = qw;
        } else {
            float gq = vin ? fmaf(-K2, qw, vin[j] * K2) : (-K2 * qw);
            shA[4 * p + h]     = qx * TWOK2;
            shA[4 * p + 2 + h] = qy * TWOK2;
            shB[4 * p + h]     = qz * TWOK2;
            shB[4 * p + 2 + h] = gq;
            if (MODE == 1) shG[2 * p + h] = vin[j] * K2;
        }
    }
    __syncthreads();

    int warp = threadIdx.x >> 5, lane = threadIdx.x & 31;
    int rsub = lane >> 3, jsub = lane & 7;         // 4 rows x 8 j-lanes
    int i = blockIdx.x * ROWSB + warp * 4 + rsub;
    if (i >= Np) return;
    int pi = i & maskP;
    float px = P[pi * 3], py = P[pi * 3 + 1], pz = P[pi * 3 + 2];
    float x2 = fmaf(pz, pz, fmaf(py, py, px * px));

    unsigned sbase = (unsigned)__cvta_generic_to_shared(sh);
    unsigned sA0 = sbase + (jsub << 4);
    unsigned sB0 = sbase + 8 * (unsigned)Nq + (jsub << 4);
    int P2 = Nq >> 1;

    if (MODE == 2) {
        ull nx = pack2(-2.0f * px, -2.0f * px);
        ull ny = pack2(-2.0f * py, -2.0f * py);
        ull nz = pack2(-2.0f * pz, -2.0f * pz);
        float mn = 3.4e38f;
        unsigned aA = sA0, aB = sB0;
#pragma unroll 4
        for (int p = jsub; p < P2; p += 8, aA += 128, aB += 128) {
            ull ax, ay, az, bw;
            lds2u64(aA, ax, ay);
            lds2u64(aB, az, bw);
            ull acc = fma2(ax, nx, bw);
            acc = fma2(ay, ny, acc);
            acc = fma2(az, nz, acc);
            float t0, t1; unpack2(acc, t0, t1);
            mn = fminf(mn, fminf(t0, t1));
        }
#pragma unroll
        for (int off = 4; off; off >>= 1)
            mn = fminf(mn, __shfl_xor_sync(0xffffffffu, mn, off));
        if (jsub == 0) voutBase[b * Np + i] = fmaxf(mn + x2, 0.0f);
        return;
    }

    // MODE 0/1: t = w + (2k q)·p  (relative; absolute = t + a0, a0 = -K2|p|^2)
    ull px2 = pack2(px, px), py2 = pack2(py, py), pz2 = pack2(pz, pz);
    float a0 = -K2 * x2;

    if (MODE == 0) {
        float m = -1e30f, s = 0.0f;
        unsigned aA = sA0, aB = sB0;
#pragma unroll 4
        for (int p = jsub; p < P2; p += 8, aA += 128, aB += 128) {
            ull ax, ay, az, bw;
            lds2u64(aA, ax, ay);
            lds2u64(aB, az, bw);
            ull acc = fma2(ax, px2, bw);
            acc = fma2(ay, py2, acc);
            acc = fma2(az, pz2, acc);
            float t0, t1; unpack2(acc, t0, t1);
            float tm = fmaxf(t0, t1);
            bool sig = tm > m - 25.0f;            // terms < 2^-25 of max: skip
            if (__any_sync(0xffffffffu, sig)) {   // warp-uniform branch
                float M = fmaxf(m, tm);
                s = fmaf(s, ex2(m - M), ex2(t0 - M) + ex2(t1 - M));
                m = M;
            }
        }
#pragma unroll
        for (int off = 4; off; off >>= 1) {       // merge across 8 j-lanes
            float om = __shfl_xor_sync(0xffffffffu, m, off);
            float os = __shfl_xor_sync(0xffffffffu, s, off);
            float M = fmaxf(m, om);
            s = fmaf(s, ex2(m - M), os * ex2(om - M));
            m = M;
        }
        if (jsub == 0)
            voutBase[b * Np + i] = fmaf(-EPS_LN2, (m + a0) + lg2(s), -epsLogN);
        return;
    }

    if (MODE == 1) {
        float m = -1e30f, s = 0.0f, sc = 0.0f;
        unsigned aA = sA0, aB = sB0;
        unsigned aG = sbase + 16 * (unsigned)Nq + (jsub << 3);
#pragma unroll 2
        for (int p = jsub; p < P2; p += 8, aA += 128, aB += 128, aG += 64) {
            ull ax, ay, az, bw;
            lds2u64(aA, ax, ay);
            lds2u64(aB, az, bw);
            ull acc = fma2(ax, px2, bw);
            acc = fma2(ay, py2, acc);
            acc = fma2(az, pz2, acc);
            float t0, t1; unpack2(acc, t0, t1);
            float tm = fmaxf(t0, t1);
            bool sig = tm > m - 25.0f;
            if (__any_sync(0xffffffffu, sig)) {
                float2 gv;
                asm volatile("ld.shared.v2.f32 {%0, %1}, [%2];"
                             : "=f"(gv.x), "=f"(gv.y) : "r"(aG));
                float M = fmaxf(m, tm);
                float e = ex2(m - M);
                float e0 = ex2(t0 - M), e1 = ex2(t1 - M);
                // C = (gk - t_abs)*EPS_LN2 ; t_abs = t + a0 ; -a0*EPS_LN2 = x2
                float C0 = fmaf(gv.x - t0, EPS_LN2, x2);
                float C1 = fmaf(gv.y - t1, EPS_LN2, x2);
                s  = fmaf(s, e, e0 + e1);
                sc = fmaf(sc, e, fmaf(e0, C0, e1 * C1));
                m = M;
            }
        }
#pragma unroll
        for (int off = 4; off; off >>= 1) {
            float om = __shfl_xor_sync(0xffffffffu, m, off);
            float os = __shfl_xor_sync(0xffffffffu, s, off);
            float oc = __shfl_xor_sync(0xffffffffu, sc, off);
            float M = fmaxf(m, om);
            float e1 = ex2(m - M), e2 = ex2(om - M);
            s  = fmaf(s,  e1, os * e2);
            sc = fmaf(sc, e1, oc * e2);
            m = M;
        }
        if (jsub == 0) voutBase[b * Np + i] = sqrtf(sc / s);
    }
}

// ---------------- reductions / final scalar outputs ----------------
__device__ __forceinline__ float blk_sum(float v, float* shp) {
    int lane = threadIdx.x & 31, wid = threadIdx.x >> 5;
#pragma unroll
    for (int off = 16; off; off >>= 1) v += __shfl_xor_sync(0xffffffffu, v, off);
    if (lane == 0) shp[wid] = v;
    __syncthreads();
    float r = 0.0f;
    if (wid == 0) {
        r = shp[lane];
#pragma unroll
        for (int off = 16; off; off >>= 1) r += __shfl_xor_sync(0xffffffffu, r, off);
    }
    __syncthreads();
    return r;
}

__global__ __launch_bounds__(1024) void finalize_kernel(float* __restrict__ out) {
    __shared__ float shp[32];
    int b = blockIdx.x;
    int t = threadIdx.x;
    const int BASE = 27648;

    float v = g_emd1r[b * 1024 + t];
    v = blk_sum(v, shp);
    if (t == 0) out[BASE + 0 + b] = v * (1.0f / 1024.0f);

    v = 0.0f;
    for (int i = t; i < 4096; i += 1024) v += g_emd2r[b * 4096 + i];
    v = blk_sum(v, shp);
    if (t == 0) out[BASE + 2 + b] = v * (1.0f / 4096.0f);

    float vs = 0.0f, vt = 0.0f;
    for (int i = t; i < 4096; i += 1024) { float d = g_d1c[b * 4096 + i]; vs += sqrtf(d); vt += d; }
    vs = blk_sum(vs, shp); vt = blk_sum(vt, shp);
    float vs2 = 0.0f, vt2 = 0.0f;
    if (t < 512) { float d = g_d2c[b * 512 + t]; vs2 = sqrtf(d); vt2 = d; }
    vs2 = blk_sum(vs2, shp); vt2 = blk_sum(vt2, shp);
    if (t == 0) {
        out[BASE + 4 + b] = (vs * (1.0f / 4096.0f) + vs2 * (1.0f / 512.0f)) * 0.5f;
        out[BASE + 8 + b] = vt * (1.0f / 4096.0f) + vt2 * (1.0f / 512.0f);
    }

    vs = 0.0f; vt = 0.0f;
    for (int i = t; i < 4096; i += 1024) { float d = g_d1f[b * 4096 + i]; vs += sqrtf(d); vt += d; }
    vs = blk_sum(vs, shp); vt = blk_sum(vt, shp);
    vs2 = 0.0f; vt2 = 0.0f;
    for (int i = t; i < 4096; i += 1024) { float d = g_d2f[b * 4096 + i]; vs2 += sqrtf(d); vt2 += d; }
    vs2 = blk_sum(vs2, shp); vt2 = blk_sum(vt2, shp);
    if (t == 0) {
        out[BASE + 6 + b]  = (vs + vs2) * (1.0f / 4096.0f) * 0.5f;
        out[BASE + 10 + b] = (vt + vt2) * (1.0f / 4096.0f);
    }
}

// ---------------- launch ----------------
extern "C" void kernel_launch(void* const* d_in, const int* in_sizes, int n_in,
                              void* d_out, int out_size) {
    const float* coarse = (const float*)d_in[0];
    const float* fine   = (const float*)d_in[1];
    const float* gt     = (const float*)d_in[2];
    const int*   iters  = (const int*)d_in[3];
    float* out = (float*)d_out;

    static cudaStream_t s1 = nullptr;
    static cudaEvent_t evFork = nullptr, evJoin = nullptr;
    if (!s1) {
        cudaStreamCreateWithFlags(&s1, cudaStreamNonBlocking);
        cudaEventCreateWithFlags(&evFork, cudaEventDisableTiming);
        cudaEventCreateWithFlags(&evJoin, cudaEventDisableTiming);
        cudaFuncSetAttribute(pair_kernel<0>, cudaFuncAttributeMaxDynamicSharedMemorySize, 84000);
        cudaFuncSetAttribute(pair_kernel<1>, cudaFuncAttributeMaxDynamicSharedMemorySize, 84000);
        cudaFuncSetAttribute(pair_kernel<2>, cudaFuncAttributeMaxDynamicSharedMemorySize, 84000);
        cudaFuncSetAttribute(fps_kernel,     cudaFuncAttributeMaxDynamicSharedMemorySize, 49400);
    }

    float *gtfps, *f1, *g1, *f2, *g2, *e1r, *e2r, *d1c, *d2c, *d1f, *d2f;
    cudaGetSymbolAddress((void**)&gtfps, g_gtfps);
    cudaGetSymbolAddress((void**)&f1, g_f1);
    cudaGetSymbolAddress((void**)&g1, g_g1);
    cudaGetSymbolAddress((void**)&f2, g_f2);
    cudaGetSymbolAddress((void**)&g2, g_g2);
    cudaGetSymbolAddress((void**)&e1r, g_emd1r);
    cudaGetSymbolAddress((void**)&e2r, g_emd2r);
    cudaGetSymbolAddress((void**)&d1c, g_d1c);
    cudaGetSymbolAddress((void**)&d2c, g_d2c);
    cudaGetSymbolAddress((void**)&d1f, g_d1f);
    cudaGetSymbolAddress((void**)&d2f, g_d2f);

    // ---- fork: FPS + EMD1 on s1 ----
    cudaEventRecord(evFork, 0);
    cudaStreamWaitEvent(s1, evFork, 0);
    fps_kernel<<<2, FPS_T, 49400, s1>>>(gt);

    cudaMemcpyAsync(out,        coarse, 2 * 512 * 3 * sizeof(float),  cudaMemcpyDeviceToDevice);
    cudaMemcpyAsync(out + 3072, fine,   2 * 4096 * 3 * sizeof(float), cudaMemcpyDeviceToDevice);

    const int GX4 = 4096 / ROWSB;   // 64
    const int GX1 = 1024 / ROWSB;   // 16
    const int GXC = 512 / ROWSB;    // 8

    // ---- stream 0: EMD2 chain ----
    for (int it = 0; it < 4; it++) {
        pair_kernel<0><<<dim3(GX4, 2), 512, 4096 * 16>>>(
            fine, 4096, IDENT_MASK, 4096 * 3, gt, 4096, IDENT_MASK, 4096 * 3,
            it == 0 ? nullptr : g2, f2, EPSLOG4096, iters, it);
        pair_kernel<0><<<dim3(GX4, 2), 512, 4096 * 16>>>(
            gt, 4096, IDENT_MASK, 4096 * 3, fine, 4096, IDENT_MASK, 4096 * 3,
            f2, g2, EPSLOG4096, iters, it);
    }
    pair_kernel<1><<<dim3(GX4, 2), 512, 4096 * 20>>>(
        fine, 4096, IDENT_MASK, 4096 * 3, gt, 4096, IDENT_MASK, 4096 * 3,
        g2, e2r, 0.0f, nullptr, 0);

    // ---- stream 0: chamfers ----
    pair_kernel<2><<<dim3(GX4, 2), 512, 512 * 16>>>(
        gt, 4096, IDENT_MASK, 4096 * 3, coarse, 512, IDENT_MASK, 512 * 3,
        nullptr, d1c, 0.0f, nullptr, 0);
    pair_kernel<2><<<dim3(GXC, 2), 512, 4096 * 16>>>(
        coarse, 512, IDENT_MASK, 512 * 3, gt, 4096, IDENT_MASK, 4096 * 3,
        nullptr, d2c, 0.0f, nullptr, 0);
    pair_kernel<2><<<dim3(GX4, 2), 512, 4096 * 16>>>(
        gt, 4096, IDENT_MASK, 4096 * 3, fine, 4096, IDENT_MASK, 4096 * 3,
        nullptr, d1f, 0.0f, nullptr, 0);
    pair_kernel<2><<<dim3(GX4, 2), 512, 4096 * 16>>>(
        fine, 4096, IDENT_MASK, 4096 * 3, gt, 4096, IDENT_MASK, 4096 * 3,
        nullptr, d2f, 0.0f, nullptr, 0);

    // ---- s1: EMD1 chain (after FPS) ----
    for (int it = 0; it < 4; it++) {
        pair_kernel<0><<<dim3(GX1, 2), 512, 1024 * 16, s1>>>(
            coarse, 1024, 511, 512 * 3, gtfps, 1024, IDENT_MASK, 1024 * 3,
            it == 0 ? nullptr : g1, f1, EPSLOG1024, iters, it);
        pair_kernel<0><<<dim3(GX1, 2), 512, 1024 * 16, s1>>>(
            gtfps, 1024, IDENT_MASK, 1024 * 3, coarse, 1024, 511, 512 * 3,
            f1, g1, EPSLOG1024, iters, it);
    }
    pair_kernel<1><<<dim3(GX1, 2), 512, 1024 * 20, s1>>>(
        coarse, 1024, 511, 512 * 3, gtfps, 1024, IDENT_MASK, 1024 * 3,
        g1, e1r, 0.0f, nullptr, 0);

    // ---- join, finalize ----
    cudaEventRecord(evJoin, s1);
    cudaStreamWaitEvent(0, evJoin, 0);
    finalize_kernel<<<2, 1024>>>(out);
}

// round 8
// speedup vs baseline: 1.5617x; 1.0442x over previous
#include <cuda_runtime.h>
#include <math.h>
#include <stdint.h>

// ---------------- constants ----------------
#define K2        72.13475204444817f     // (1/EPS)*log2(e)
#define TWOK2     144.26950408889634f    // 2*K2
#define EPS_LN2   0.013862943611198906f  // EPS*ln(2) == 1/K2
#define EPSLOG1024 0.13862943611198905f
#define EPSLOG4096 0.16635532333438687f
#define IDENT_MASK 0x7FFFFFFF
typedef unsigned long long ull;

// ---------------- scratch ----------------
__device__ float g_gtfps[2 * 1024 * 3];
__device__ float g_f1[2 * 1024];
__device__ float g_g1[2 * 1024];
__device__ float g_f2[2 * 4096];
__device__ float g_g2[2 * 4096];
__device__ float g_emd1r[2 * 1024];
__device__ float g_emd2r[2 * 4096];
__device__ float g_d1c[2 * 4096];
__device__ float g_d2c[2 * 512];
__device__ float g_d1f[2 * 4096];
__device__ float g_d2f[2 * 4096];

// ---------------- fast math helpers ----------------
__device__ __forceinline__ float ex2(float x) {
    float y; asm("ex2.approx.ftz.f32 %0, %1;" : "=f"(y) : "f"(x)); return y;
}
__device__ __forceinline__ float lg2(float x) {
    float y; asm("lg2.approx.f32 %0, %1;" : "=f"(y) : "f"(x)); return y;
}
__device__ __forceinline__ ull pack2(float a, float b) {
    ull r; asm("mov.b64 %0, {%1, %2};" : "=l"(r) : "f"(a), "f"(b)); return r;
}
__device__ __forceinline__ void unpack2(ull v, float& a, float& b) {
    asm("mov.b64 {%0, %1}, %2;" : "=f"(a), "=f"(b) : "l"(v));
}
__device__ __forceinline__ ull fma2(ull a, ull b, ull c) {
    ull d; asm("fma.rn.f32x2 %0, %1, %2, %3;" : "=l"(d) : "l"(a), "l"(b), "l"(c)); return d;
}
__device__ __forceinline__ ull add2(ull a, ull b) {
    ull d; asm("add.rn.f32x2 %0, %1, %2;" : "=l"(d) : "l"(a), "l"(b)); return d;
}
__device__ __forceinline__ void lds2u64(unsigned addr, ull& a, ull& b) {
    asm volatile("ld.shared.v2.u64 {%0, %1}, [%2];" : "=l"(a), "=l"(b) : "r"(addr));
}

// ---------------- FPS: 256 threads, 16 pts/thread in registers ----------------
#define FPS_T 256
__global__ __launch_bounds__(FPS_T) void fps_kernel(const float* __restrict__ gt) {
    extern __shared__ float sh[];
    float* SX = sh;
    float* SY = sh + 4096;
    float* SZ = sh + 8192;
    int* swm  = (int*)(sh + 12288);   // [8] per-warp max bits
    int* sIdx = (int*)(sh + 12296);   // [2] winner idx, parity dbl-buffered

    int b = blockIdx.x;
    const float* P = gt + b * 4096 * 3;
    float* outp = g_gtfps + b * 1024 * 3;
    int t = threadIdx.x, lane = t & 31, wid = t >> 5;

    const float4* P4 = (const float4*)P;
    for (int k = t; k < 3072; k += FPS_T) {
        float4 v = P4[k];
        int e = 4 * k;
        float c[4] = {v.x, v.y, v.z, v.w};
#pragma unroll
        for (int q = 0; q < 4; q++) {
            int ei = e + q;
            sh[(ei % 3) * 4096 + (ei / 3)] = c[q];
        }
    }
    if (t == 0) { sIdx[0] = 0x7FFFFFFF; sIdx[1] = 0x7FFFFFFF; }
    __syncthreads();

    int base = t * 16;                      // contiguous ownership -> exact tiebreak
    ull qx[8], qy[8], qz[8], qw[8];
    float dm[16];
#pragma unroll
    for (int j = 0; j < 8; j++) {
        float x0 = SX[base + 2 * j], x1 = SX[base + 2 * j + 1];
        float y0 = SY[base + 2 * j], y1 = SY[base + 2 * j + 1];
        float z0 = SZ[base + 2 * j], z1 = SZ[base + 2 * j + 1];
        qx[j] = pack2(x0, x1); qy[j] = pack2(y0, y1); qz[j] = pack2(z0, z1);
        qw[j] = pack2(fmaf(z0, z0, fmaf(y0, y0, x0 * x0)),
                      fmaf(z1, z1, fmaf(y1, y1, x1 * x1)));
        dm[2 * j] = 1e10f; dm[2 * j + 1] = 1e10f;
    }

    float lx = SX[0], ly = SY[0], lz = SZ[0];
    if (t == 0) { outp[0] = lx; outp[1] = ly; outp[2] = lz; }

    for (int step = 1; step < 1024; step++) {
        float ll = fmaf(lz, lz, fmaf(ly, ly, lx * lx));
        ull nx = pack2(-2.0f * lx, -2.0f * lx);
        ull ny = pack2(-2.0f * ly, -2.0f * ly);
        ull nz = pack2(-2.0f * lz, -2.0f * lz);
        ull l2 = pack2(ll, ll);
        float mv = -1.0f;
#pragma unroll
        for (int j = 0; j < 8; j++) {
            ull d = fma2(qx[j], nx, qw[j]);
            d = fma2(qy[j], ny, d);
            d = fma2(qz[j], nz, d);
            d = add2(d, l2);
            float d0, d1; unpack2(d, d0, d1);
            dm[2 * j]     = fminf(dm[2 * j], d0);
            dm[2 * j + 1] = fminf(dm[2 * j + 1], d1);
            mv = fmaxf(mv, fmaxf(dm[2 * j], dm[2 * j + 1]));
        }
        int mb = __float_as_int(mv);               // d>=0 -> bits monotone
        int M = __reduce_max_sync(0xffffffffu, mb);
        if (lane == 0) swm[wid] = M;
        __syncthreads();
        int MM = max(max(max(swm[0], swm[1]), max(swm[2], swm[3])),
                     max(max(swm[4], swm[5]), max(swm[6], swm[7])));
        if (mb == MM) {                            // winning thread(s) only
            float Mf = __int_as_float(MM);
            int idx = 0x7FFFFFFF;
#pragma unroll
            for (int j = 15; j >= 0; j--)
                if (dm[j] == Mf) idx = base + j;   // downward scan -> lowest idx
            atomicMin(&sIdx[step & 1], idx);
        }
        __syncthreads();
        int wi = sIdx[step & 1];
        lx = SX[wi]; ly = SY[wi]; lz = SZ[wi];
        if (t == 0) {
            outp[step * 3 + 0] = lx; outp[step * 3 + 1] = ly; outp[step * 3 + 2] = lz;
            sIdx[(step + 1) & 1] = 0x7FFFFFFF;     // reset other slot
        }
    }
}

// ---------------- pairwise kernel (templated rows/warp) ----------------
// RPW rows per warp, JL = 32/RPW j-lanes. 512 threads, 16*RPW rows per block.
// smem: shA[p]={x0,x1,y0,y1}*TWOK2, shB[p]={z0,z1,w0,w1}, w = K2*g - K2*|q|^2
// MODE 0: Sinkhorn half-pass (online-flat LSE + warp-vote skip)
// MODE 1: final EMD row; MODE 2: chamfer min
template <int MODE, int RPW>
__global__ __launch_bounds__(512) void pair_kernel(
    const float* __restrict__ Pbase, int Np, int maskP, int strideP,
    const float* __restrict__ Qbase, int Nq, int maskQ, int strideQ,
    const float* __restrict__ vinBase, float* __restrict__ voutBase,
    float epsLogN, const int* __restrict__ itersPtr, int myIter)
{
    constexpr int JL = 32 / RPW;
    if (itersPtr && myIter >= *itersPtr) return;
    int b = blockIdx.y;
    const float* P = Pbase + b * strideP;
    const float* Q = Qbase + b * strideQ;
    const float* vin = vinBase ? (vinBase + b * Nq) : nullptr;

    extern __shared__ float sh[];
    float* shA = sh;
    float* shB = sh + 2 * Nq;
    float* shG = sh + 4 * Nq;   // MODE 1 only

    for (int j = threadIdx.x; j < Nq; j += blockDim.x) {
        int qj = j & maskQ;
        float qx = Q[qj * 3], qy = Q[qj * 3 + 1], qz = Q[qj * 3 + 2];
        float qw = fmaf(qz, qz, fmaf(qy, qy, qx * qx));
        int p = j >> 1, h = j & 1;
        if (MODE == 2) {
            shA[4 * p + h]     = qx;
            shA[4 * p + 2 + h] = qy;
            shB[4 * p + h]     = qz;
            shB[4 * p + 2 + h] = qw;
        } else {
            float gq = vin ? fmaf(-K2, qw, vin[j] * K2) : (-K2 * qw);
            shA[4 * p + h]     = qx * TWOK2;
            shA[4 * p + 2 + h] = qy * TWOK2;
            shB[4 * p + h]     = qz * TWOK2;
            shB[4 * p + 2 + h] = gq;
            if (MODE == 1) shG[2 * p + h] = vin[j] * K2;
        }
    }
    __syncthreads();

    int warp = threadIdx.x >> 5, lane = threadIdx.x & 31;
    int rsub = lane / JL, jsub = lane % JL;
    int i = blockIdx.x * (16 * RPW) + warp * RPW + rsub;
    if (i >= Np) return;
    int pi = i & maskP;
    float px = P[pi * 3], py = P[pi * 3 + 1], pz = P[pi * 3 + 2];
    float x2 = fmaf(pz, pz, fmaf(py, py, px * px));

    unsigned sbase = (unsigned)__cvta_generic_to_shared(sh);
    unsigned sA0 = sbase + (jsub << 4);
    unsigned sB0 = sbase + 8 * (unsigned)Nq + (jsub << 4);
    int P2 = Nq >> 1;

    if (MODE == 2) {
        ull nx = pack2(-2.0f * px, -2.0f * px);
        ull ny = pack2(-2.0f * py, -2.0f * py);
        ull nz = pack2(-2.0f * pz, -2.0f * pz);
        float mn = 3.4e38f;
        unsigned aA = sA0, aB = sB0;
#pragma unroll 8
        for (int p = jsub; p < P2; p += JL, aA += JL * 16, aB += JL * 16) {
            ull ax, ay, az, bw;
            lds2u64(aA, ax, ay);
            lds2u64(aB, az, bw);
            ull acc = fma2(ax, nx, bw);
            acc = fma2(ay, ny, acc);
            acc = fma2(az, nz, acc);
            float t0, t1; unpack2(acc, t0, t1);
            mn = fminf(mn, fminf(t0, t1));
        }
#pragma unroll
        for (int off = JL / 2; off; off >>= 1)
            mn = fminf(mn, __shfl_xor_sync(0xffffffffu, mn, off));
        if (jsub == 0) voutBase[b * Np + i] = fmaxf(mn + x2, 0.0f);
        return;
    }

    // MODE 0/1: t = w + (2k q)·p  (relative; absolute = t + a0, a0 = -K2|p|^2)
    ull px2 = pack2(px, px), py2 = pack2(py, py), pz2 = pack2(pz, pz);
    float a0 = -K2 * x2;

    if (MODE == 0) {
        float m = -1e30f, s = 0.0f;
        unsigned aA = sA0, aB = sB0;
#pragma unroll 8
        for (int p = jsub; p < P2; p += JL, aA += JL * 16, aB += JL * 16) {
            ull ax, ay, az, bw;
            lds2u64(aA, ax, ay);
            lds2u64(aB, az, bw);
            ull acc = fma2(ax, px2, bw);
            acc = fma2(ay, py2, acc);
            acc = fma2(az, pz2, acc);
            float t0, t1; unpack2(acc, t0, t1);
            float tm = fmaxf(t0, t1);
            bool sig = tm > m - 25.0f;            // terms < 2^-25 of max: skip
            if (__any_sync(0xffffffffu, sig)) {   // warp-uniform branch
                float M = fmaxf(m, tm);
                s = fmaf(s, ex2(m - M), ex2(t0 - M) + ex2(t1 - M));
                m = M;
            }
        }
#pragma unroll
        for (int off = JL / 2; off; off >>= 1) {
            float om = __shfl_xor_sync(0xffffffffu, m, off);
            float os = __shfl_xor_sync(0xffffffffu, s, off);
            float M = fmaxf(m, om);
            s = fmaf(s, ex2(m - M), os * ex2(om - M));
            m = M;
        }
        if (jsub == 0)
            voutBase[b * Np + i] = fmaf(-EPS_LN2, (m + a0) + lg2(s), -epsLogN);
        return;
    }

    if (MODE == 1) {
        float m = -1e30f, s = 0.0f, sc = 0.0f;
        unsigned aA = sA0, aB = sB0;
        unsigned aG = sbase + 16 * (unsigned)Nq + (jsub << 3);
#pragma unroll 4
        for (int p = jsub; p < P2; p += JL, aA += JL * 16, aB += JL * 16, aG += JL * 8) {
            ull ax, ay, az, bw;
            lds2u64(aA, ax, ay);
            lds2u64(aB, az, bw);
            ull acc = fma2(ax, px2, bw);
            acc = fma2(ay, py2, acc);
            acc = fma2(az, pz2, acc);
            float t0, t1; unpack2(acc, t0, t1);
            float tm = fmaxf(t0, t1);
            bool sig = tm > m - 25.0f;
            if (__any_sync(0xffffffffu, sig)) {
                float2 gv;
                asm volatile("ld.shared.v2.f32 {%0, %1}, [%2];"
                             : "=f"(gv.x), "=f"(gv.y) : "r"(aG));
                float M = fmaxf(m, tm);
                float e = ex2(m - M);
                float e0 = ex2(t0 - M), e1 = ex2(t1 - M);
                float C0 = fmaf(gv.x - t0, EPS_LN2, x2);
                float C1 = fmaf(gv.y - t1, EPS_LN2, x2);
                s  = fmaf(s, e, e0 + e1);
                sc = fmaf(sc, e, fmaf(e0, C0, e1 * C1));
                m = M;
            }
        }
#pragma unroll
        for (int off = JL / 2; off; off >>= 1) {
            float om = __shfl_xor_sync(0xffffffffu, m, off);
            float os = __shfl_xor_sync(0xffffffffu, s, off);
            float oc = __shfl_xor_sync(0xffffffffu, sc, off);
            float M = fmaxf(m, om);
            float e1 = ex2(m - M), e2 = ex2(om - M);
            s  = fmaf(s,  e1, os * e2);
            sc = fmaf(sc, e1, oc * e2);
            m = M;
        }
        if (jsub == 0) voutBase[b * Np + i] = sqrtf(sc / s);
    }
}

// ---------------- reductions / final scalar outputs ----------------
__device__ __forceinline__ float blk_sum(float v, float* shp) {
    int lane = threadIdx.x & 31, wid = threadIdx.x >> 5;
#pragma unroll
    for (int off = 16; off; off >>= 1) v += __shfl_xor_sync(0xffffffffu, v, off);
    if (lane == 0) shp[wid] = v;
    __syncthreads();
    float r = 0.0f;
    if (wid == 0) {
        r = shp[lane];
#pragma unroll
        for (int off = 16; off; off >>= 1) r += __shfl_xor_sync(0xffffffffu, r, off);
    }
    __syncthreads();
    return r;
}

__global__ __launch_bounds__(1024) void finalize_kernel(float* __restrict__ out) {
    __shared__ float shp[32];
    int b = blockIdx.x;
    int t = threadIdx.x;
    const int BASE = 27648;

    float v = g_emd1r[b * 1024 + t];
    v = blk_sum(v, shp);
    if (t == 0) out[BASE + 0 + b] = v * (1.0f / 1024.0f);

    v = 0.0f;
    for (int i = t; i < 4096; i += 1024) v += g_emd2r[b * 4096 + i];
    v = blk_sum(v, shp);
    if (t == 0) out[BASE + 2 + b] = v * (1.0f / 4096.0f);

    float vs = 0.0f, vt = 0.0f;
    for (int i = t; i < 4096; i += 1024) { float d = g_d1c[b * 4096 + i]; vs += sqrtf(d); vt += d; }
    vs = blk_sum(vs, shp); vt = blk_sum(vt, shp);
    float vs2 = 0.0f, vt2 = 0.0f;
    if (t < 512) { float d = g_d2c[b * 512 + t]; vs2 = sqrtf(d); vt2 = d; }
    vs2 = blk_sum(vs2, shp); vt2 = blk_sum(vt2, shp);
    if (t == 0) {
        out[BASE + 4 + b] = (vs * (1.0f / 4096.0f) + vs2 * (1.0f / 512.0f)) * 0.5f;
        out[BASE + 8 + b] = vt * (1.0f / 4096.0f) + vt2 * (1.0f / 512.0f);
    }

    vs = 0.0f; vt = 0.0f;
    for (int i = t; i < 4096; i += 1024) { float d = g_d1f[b * 4096 + i]; vs += sqrtf(d); vt += d; }
    vs = blk_sum(vs, shp); vt = blk_sum(vt, shp);
    vs2 = 0.0f; vt2 = 0.0f;
    for (int i = t; i < 4096; i += 1024) { float d = g_d2f[b * 4096 + i]; vs2 += sqrtf(d); vt2 += d; }
    vs2 = blk_sum(vs2, shp); vt2 = blk_sum(vt2, shp);
    if (t == 0) {
        out[BASE + 6 + b]  = (vs + vs2) * (1.0f / 4096.0f) * 0.5f;
        out[BASE + 10 + b] = (vt + vt2) * (1.0f / 4096.0f);
    }
}

// ---------------- launch ----------------
extern "C" void kernel_launch(void* const* d_in, const int* in_sizes, int n_in,
                              void* d_out, int out_size) {
    const float* coarse = (const float*)d_in[0];
    const float* fine   = (const float*)d_in[1];
    const float* gt     = (const float*)d_in[2];
    const int*   iters  = (const int*)d_in[3];
    float* out = (float*)d_out;

    static cudaStream_t s1 = nullptr;
    static cudaEvent_t evFork = nullptr, evJoin = nullptr;
    if (!s1) {
        cudaStreamCreateWithFlags(&s1, cudaStreamNonBlocking);
        cudaEventCreateWithFlags(&evFork, cudaEventDisableTiming);
        cudaEventCreateWithFlags(&evJoin, cudaEventDisableTiming);
        cudaFuncSetAttribute(pair_kernel<0,1>, cudaFuncAttributeMaxDynamicSharedMemorySize, 84000);
        cudaFuncSetAttribute(pair_kernel<0,2>, cudaFuncAttributeMaxDynamicSharedMemorySize, 84000);
        cudaFuncSetAttribute(pair_kernel<1,1>, cudaFuncAttributeMaxDynamicSharedMemorySize, 84000);
        cudaFuncSetAttribute(pair_kernel<1,2>, cudaFuncAttributeMaxDynamicSharedMemorySize, 84000);
        cudaFuncSetAttribute(pair_kernel<2,1>, cudaFuncAttributeMaxDynamicSharedMemorySize, 84000);
        cudaFuncSetAttribute(pair_kernel<2,2>, cudaFuncAttributeMaxDynamicSharedMemorySize, 84000);
        cudaFuncSetAttribute(fps_kernel,       cudaFuncAttributeMaxDynamicSharedMemorySize, 49400);
    }

    float *gtfps, *f1, *g1, *f2, *g2, *e1r, *e2r, *d1c, *d2c, *d1f, *d2f;
    cudaGetSymbolAddress((void**)&gtfps, g_gtfps);
    cudaGetSymbolAddress((void**)&f1, g_f1);
    cudaGetSymbolAddress((void**)&g1, g_g1);
    cudaGetSymbolAddress((void**)&f2, g_f2);
    cudaGetSymbolAddress((void**)&g2, g_g2);
    cudaGetSymbolAddress((void**)&e1r, g_emd1r);
    cudaGetSymbolAddress((void**)&e2r, g_emd2r);
    cudaGetSymbolAddress((void**)&d1c, g_d1c);
    cudaGetSymbolAddress((void**)&d2c, g_d2c);
    cudaGetSymbolAddress((void**)&d1f, g_d1f);
    cudaGetSymbolAddress((void**)&d2f, g_d2f);

    // ---- fork: FPS + EMD1 on s1 ----
    cudaEventRecord(evFork, 0);
    cudaStreamWaitEvent(s1, evFork, 0);
    fps_kernel<<<2, FPS_T, 49400, s1>>>(gt);

    cudaMemcpyAsync(out,        coarse, 2 * 512 * 3 * sizeof(float),  cudaMemcpyDeviceToDevice);
    cudaMemcpyAsync(out + 3072, fine,   2 * 4096 * 3 * sizeof(float), cudaMemcpyDeviceToDevice);

    // ---- stream 0: EMD2 chain (RPW=2: 128x2 = 256 blocks) ----
    for (int it = 0; it < 4; it++) {
        pair_kernel<0,2><<<dim3(128, 2), 512, 4096 * 16>>>(
            fine, 4096, IDENT_MASK, 4096 * 3, gt, 4096, IDENT_MASK, 4096 * 3,
            it == 0 ? nullptr : g2, f2, EPSLOG4096, iters, it);
        pair_kernel<0,2><<<dim3(128, 2), 512, 4096 * 16>>>(
            gt, 4096, IDENT_MASK, 4096 * 3, fine, 4096, IDENT_MASK, 4096 * 3,
            f2, g2, EPSLOG4096, iters, it);
    }
    pair_kernel<1,2><<<dim3(128, 2), 512, 4096 * 20>>>(
        fine, 4096, IDENT_MASK, 4096 * 3, gt, 4096, IDENT_MASK, 4096 * 3,
        g2, e2r, 0.0f, nullptr, 0);

    // ---- stream 0: chamfers ----
    pair_kernel<2,2><<<dim3(128, 2), 512, 512 * 16>>>(
        gt, 4096, IDENT_MASK, 4096 * 3, coarse, 512, IDENT_MASK, 512 * 3,
        nullptr, d1c, 0.0f, nullptr, 0);
    pair_kernel<2,1><<<dim3(32, 2), 512, 4096 * 16>>>(
        coarse, 512, IDENT_MASK, 512 * 3, gt, 4096, IDENT_MASK, 4096 * 3,
        nullptr, d2c, 0.0f, nullptr, 0);
    pair_kernel<2,2><<<dim3(128, 2), 512, 4096 * 16>>>(
        gt, 4096, IDENT_MASK, 4096 * 3, fine, 4096, IDENT_MASK, 4096 * 3,
        nullptr, d1f, 0.0f, nullptr, 0);
    pair_kernel<2,2><<<dim3(128, 2), 512, 4096 * 16>>>(
        fine, 4096, IDENT_MASK, 4096 * 3, gt, 4096, IDENT_MASK, 4096 * 3,
        nullptr, d2f, 0.0f, nullptr, 0);

    // ---- s1: EMD1 chain (after FPS; RPW=1: 64x2 = 128 blocks, 2048 warps) ----
    for (int it = 0; it < 4; it++) {
        pair_kernel<0,1><<<dim3(64, 2), 512, 1024 * 16, s1>>>(
            coarse, 1024, 511, 512 * 3, gtfps, 1024, IDENT_MASK, 1024 * 3,
            it == 0 ? nullptr : g1, f1, EPSLOG1024, iters, it);
        pair_kernel<0,1><<<dim3(64, 2), 512, 1024 * 16, s1>>>(
            gtfps, 1024, IDENT_MASK, 1024 * 3, coarse, 1024, 511, 512 * 3,
            f1, g1, EPSLOG1024, iters, it);
    }
    pair_kernel<1,1><<<dim3(64, 2), 512, 1024 * 20, s1>>>(
        coarse, 1024, 511, 512 * 3, gtfps, 1024, IDENT_MASK, 1024 * 3,
        g1, e1r, 0.0f, nullptr, 0);

    // ---- join, finalize ----
    cudaEventRecord(evJoin, s1);
    cudaStreamWaitEvent(0, evJoin, 0);
    finalize_kernel<<<2, 1024>>>(out);
}